// round 8
// baseline (speedup 1.0000x reference)
#include <cuda_runtime.h>

namespace {
constexpr int NTHREADS = 256;
constexpr int ST     = 33;             // smem tile stride (32 atoms + 1 pad)
constexpr int TILE   = 32;
constexpr int NCOEF  = 316;            // 32*1 + 24*3 + 20*5 + 16*7
constexpr int NPAIR  = 1174;           // 528 + 300 + 210 + 136
constexpr int NRAD   = 64;
constexpr int NSP    = 4;
constexpr int NFEAT  = NPAIR + NRAD + 1;   // 1239
constexpr int FSPLIT = 2;
constexpr int SMAX   = 256;
constexpr int NCOLS  = NSP * NFEAT;    // 4956
constexpr int NGRP   = 328;            // pair groups (i2 blocked by 4): 144+84+60+40
}

__device__ int g_run[SMAX * 5];        // per structure: run starts sp=0..3, then end
__device__ int g_order[1 << 16];       // atom indices sorted by (structure, species)

// One block per structure: binary-search bounds in sorted structure_index, then
// deterministically order atoms by species. Two passes: count, then scatter with
// warp-major, lane-minor rank (deterministic, no atomic-order dependence).
__global__ void setup_kernel(const int* __restrict__ sidx,
                             const int* __restrict__ species, int n_atoms) {
    const int s    = blockIdx.x;
    const int tid  = threadIdx.x;
    const int lane = tid & 31;
    const int wid  = tid >> 5;
    __shared__ int cnt[NSP], off[NSP], wcnt[8][NSP];

    int lo = 0, hi = n_atoms;
    while (lo < hi) { int mid = (lo + hi) >> 1; if (sidx[mid] < s) lo = mid + 1; else hi = mid; }
    const int a0 = lo;
    lo = a0; hi = n_atoms;
    while (lo < hi) { int mid = (lo + hi) >> 1; if (sidx[mid] < s + 1) lo = mid + 1; else hi = mid; }
    const int a1 = lo;

    if (tid < NSP) cnt[tid] = 0;
    __syncthreads();
    // pass 1: count species over the whole structure
    for (int chunk = a0; chunk < a1; chunk += NTHREADS) {
        const int n  = min(NTHREADS, a1 - chunk);
        const int sp = (tid < n) ? species[chunk + tid] : -1;
        const unsigned m = __match_any_sync(0xFFFFFFFFu, sp);
        if (sp >= 0 && (m & ((1u << lane) - 1u)) == 0)   // group leader in warp
            atomicAdd(&cnt[sp], __popc(m));
    }
    __syncthreads();
    if (tid == 0) {
        int p = a0;
#pragma unroll
        for (int q = 0; q < NSP; ++q) { g_run[s * 5 + q] = p; off[q] = p; p += cnt[q]; }
        g_run[s * 5 + 4] = p;
    }
    __syncthreads();
    // pass 2: scatter with deterministic rank
    for (int chunk = a0; chunk < a1; chunk += NTHREADS) {
        const int n  = min(NTHREADS, a1 - chunk);
        const int sp = (tid < n) ? species[chunk + tid] : -1;
        const unsigned m = __match_any_sync(0xFFFFFFFFu, sp);
        const int rank_w = __popc(m & ((1u << lane) - 1u));
        if (lane < NSP) wcnt[wid][lane] = 0;
        __syncthreads();
        if (sp >= 0 && rank_w == 0) wcnt[wid][sp] = __popc(m);
        __syncthreads();
        if (sp >= 0) {
            int pre = 0;
            for (int w = 0; w < wid; ++w) pre += wcnt[w][sp];
            g_order[off[sp] + pre + rank_w] = chunk + tid;
        }
        __syncthreads();
        if (tid < NSP) {
            int tot = 0;
#pragma unroll
            for (int w = 0; w < 8; ++w) tot += wcnt[w][tid];
            off[tid] += tot;
        }
        __syncthreads();
    }
}

// Accumulate 4 pair features (shared i1, blocked i2) over one species run.
template<int D>
__device__ __forceinline__ void accum_group(const float* __restrict__ S,
                                            int b1off, const int (&rowoff)[4],
                                            int t0, int t1, float (&acc)[4]) {
#pragma unroll 2
    for (int t = t0; t < t1; ++t) {
        float b1v[D];
#pragma unroll
        for (int j = 0; j < D; ++j) b1v[j] = S[b1off + j * ST + t];
#pragma unroll
        for (int c = 0; c < 4; ++c) {
#pragma unroll
            for (int j = 0; j < D; ++j) {
                float y = S[rowoff[c] + (D - 1 - j) * ST + t];
                acc[c] = (j & 1) ? fmaf(-b1v[j], y, acc[c]) : fmaf(b1v[j], y, acc[c]);
            }
        }
    }
}

template<int D>
__device__ __forceinline__ void accum_all(const float* __restrict__ S,
                                          int b1off, const int (&rowoff)[4],
                                          const int (&run)[5], int base, int nt,
                                          float (&facc)[NSP][4]) {
#pragma unroll
    for (int sp = 0; sp < NSP; ++sp) {
        const int t0 = max(run[sp] - base, 0);
        const int t1 = min(run[sp + 1] - base, nt);
        accum_group<D>(S, b1off, rowoff, t0, t1, facc[sp]);
    }
}

__global__ __launch_bounds__(NTHREADS, 3)
void le_ace_kernel(const float* __restrict__ comp,
                   const float* __restrict__ radial,
                   const float* __restrict__ sph0,
                   const float* __restrict__ sph1,
                   const float* __restrict__ sph2,
                   const float* __restrict__ sph3,
                   float* __restrict__ out,
                   int n_atoms) {
    __shared__ float tileS[NCOEF * ST];     // 41.7 KB
    __shared__ int   sord[TILE];

    const int tid  = threadIdx.x;
    const int lane = tid & 31;
    const int wid  = tid >> 5;
    const int s    = blockIdx.x;
    const int u    = blockIdx.y * NTHREADS + tid;   // work unit id, [0, 512)

    // per-l tables (local const -> fully folded, device-legal)
    const int GCUM1 = 144, GCUM2 = 228, GCUM3 = 288;
    const int QLa[4]    = {32, 24, 20, 16};
    const int COFFa[4]  = {0, 32, 104, 204};
    const int FBASEa[4] = {0, 528, 828, 1038};

    // ---- decode unit ----
    // kind: 1 = pair group, 0 = radial (jrad), -1 = comp, -2 = inactive
    int kind = -2, l = 0, d = 1, i1 = 0, ibase = 0, nv = 0, jrad = 0;
    int b1off = 0, rowoff[4] = {0, 0, 0, 0};
    if (u < NGRP) {
        kind = 1;
        int gc = 0;
        if (u < GCUM1)      { l = 0; gc = 0; }
        else if (u < GCUM2) { l = 1; gc = GCUM1; }
        else if (u < GCUM3) { l = 2; gc = GCUM2; }
        else                { l = 3; gc = GCUM3; }
        const int q = QLa[l];
        d = 2 * l + 1;
        int rem = u - gc;
        int g = 0;
        while (rem >= q - 4 * g) { rem -= q - 4 * g; ++g; }   // blocked triangular
        i1    = rem;
        ibase = i1 + 4 * g;
        nv    = min(4, q - ibase);
        b1off = (COFFa[l] + i1 * d) * ST;
#pragma unroll
        for (int c = 0; c < 4; ++c) {
            int i2c = min(ibase + c, q - 1);
            rowoff[c] = (COFFa[l] + i2c * d) * ST;
        }
    } else if (u < NGRP + NRAD) {
        kind = 0; jrad = u - NGRP;
    } else if (u == NGRP + NRAD) {
        kind = -1;
    }

    float facc[NSP][4];
#pragma unroll
    for (int sp = 0; sp < NSP; ++sp)
#pragma unroll
        for (int c = 0; c < 4; ++c) facc[sp][c] = 0.f;

    int run[5];
#pragma unroll
    for (int r = 0; r < 5; ++r) run[r] = g_run[s * 5 + r];
    const int a0 = run[0];
    const int a1 = run[4];

    for (int base = a0; base < a1; base += TILE) {
        const int nt = min(TILE, a1 - base);
        __syncthreads();                     // previous tile fully consumed
        if (tid < TILE) sord[tid] = (base + tid < a1) ? g_order[base + tid] : -1;
        __syncthreads();
        const int o0 = sord[lane];
        for (int c = wid; c < NCOEF; c += 8) {
            const float* p; int r;
            if (c < 32)       { p = sph0; r = c;       }
            else if (c < 104) { p = sph1; r = c - 32;  }
            else if (c < 204) { p = sph2; r = c - 104; }
            else              { p = sph3; r = c - 204; }
            tileS[c * ST + lane] = (o0 >= 0) ? p[(long)r * n_atoms + o0] : 0.f;
        }
        __syncthreads();

        if (kind == 1) {
            switch (d) {
                case 1:  accum_all<1>(tileS, b1off, rowoff, run, base, nt, facc); break;
                case 3:  accum_all<3>(tileS, b1off, rowoff, run, base, nt, facc); break;
                case 5:  accum_all<5>(tileS, b1off, rowoff, run, base, nt, facc); break;
                default: accum_all<7>(tileS, b1off, rowoff, run, base, nt, facc); break;
            }
        } else if (kind == 0) {
#pragma unroll
            for (int sp = 0; sp < NSP; ++sp) {
                const int t0 = max(run[sp] - base, 0);
                const int t1 = min(run[sp + 1] - base, nt);
                float acc = 0.f;
#pragma unroll 4
                for (int t = t0; t < t1; ++t)
                    acc += radial[(long)sord[t] * NRAD + jrad];
                facc[sp][0] += acc;
            }
        } else if (kind == -1) {
#pragma unroll
            for (int sp = 0; sp < NSP; ++sp) {
                const int t0 = max(run[sp] - base, 0);
                const int t1 = min(run[sp + 1] - base, nt);
                float acc = 0.f;
                for (int t = t0; t < t1; ++t)
                    acc += comp[sord[t]];
                facc[sp][0] += acc;
            }
        }
    }

    // ---- write: each (feature, species) owned by exactly one thread ----
    if (kind == 1) {
        const float invsq[4] = {1.0f, 0.5773502691896258f,
                                0.4472135954999579f, 0.3779644730092272f};
        const int q = QLa[l];
        const int rowstart = i1 * q - (i1 * (i1 - 1)) / 2;   // triangular row start
#pragma unroll
        for (int c = 0; c < 4; ++c) {
            if (c >= nv) break;
            const int i2 = ibase + c;
            const int f  = FBASEa[l] + rowstart + (i2 - i1);
            const float sc = invsq[l] * ((i1 == i2) ? 1.0f : 1.4142135623730951f);
#pragma unroll
            for (int sp = 0; sp < NSP; ++sp) {
                const int col = NSP + NSP * NRAD + sp * NPAIR + f;
                out[s * NCOLS + col] = sc * facc[sp][c];
            }
        }
    } else if (kind == 0) {
#pragma unroll
        for (int sp = 0; sp < NSP; ++sp)
            out[s * NCOLS + NSP + sp * NRAD + jrad] = facc[sp][0];
    } else if (kind == -1) {
#pragma unroll
        for (int sp = 0; sp < NSP; ++sp)
            out[s * NCOLS + sp] = facc[sp][0];
    }
}

extern "C" void kernel_launch(void* const* d_in, const int* in_sizes, int n_in,
                              void* d_out, int out_size) {
    const float* comp    = (const float*)d_in[0];
    const float* radial  = (const float*)d_in[1];
    const float* sph0    = (const float*)d_in[2];
    const float* sph1    = (const float*)d_in[3];
    const float* sph2    = (const float*)d_in[4];
    const float* sph3    = (const float*)d_in[5];
    const int*   sidx    = (const int*)d_in[6];
    const int*   species = (const int*)d_in[7];
    float*       out     = (float*)d_out;

    int n_atoms = in_sizes[0];
    int S       = out_size / NCOLS;
    if (S > SMAX) S = SMAX;

    setup_kernel<<<S, NTHREADS>>>(sidx, species, n_atoms);
    dim3 grid(S, FSPLIT);
    le_ace_kernel<<<grid, NTHREADS>>>(comp, radial, sph0, sph1, sph2, sph3,
                                      out, n_atoms);
}